// round 6
// baseline (speedup 1.0000x reference)
#include <cuda_runtime.h>

#define NN 768
#define FD 64
#define DE 32
#define HD 64
#define H2 128
#define EGRID 148

// Scratch (allocation-free rule: __device__ globals), 16B-aligned
__device__ __align__(16) float g_P [NN * HD];
__device__ __align__(16) float g_Q [NN * HD];
__device__ __align__(16) float g_X1[NN * HD];
__device__ __align__(16) float g_X2[NN * HD];
__device__ unsigned g_cnt;          // zero-init at load; reset by final_kernel
__device__ unsigned g_edges[NN * NN];

// Fused prep: (optional) adjacency compaction + P/Q GEMMs + zero next accumulator.
// P[i,h] = x_i @ (W[0:64]-W[64:128]) + ba ;  Q[j,h] = x_j @ W[64:128]
__global__ __launch_bounds__(256) void prep_kernel(
    const float* __restrict__ A,   // null => skip compaction
    const float* __restrict__ x, const float* __restrict__ W,
    const float* __restrict__ ba, float* __restrict__ P,
    float* __restrict__ Q, float* __restrict__ Xz)
{
    __shared__ float sW[2 * FD * HD];   // 32 KB
    __shared__ float sx[4][FD];
    __shared__ unsigned lcnt[4], lbase[4];

    const int tid = threadIdx.x;
    const int b   = blockIdx.x;
    const int nl  = tid >> 6;
    const int h   = tid & 63;
    const int node = b * 4 + nl;

    // zero accumulator slice (192 blocks x 256 threads x float4 = 768*64)
    {
        unsigned g = b * 256u + (unsigned)tid;
        if (g < (NN * HD) / 4) ((float4*)Xz)[g] = make_float4(0.f, 0.f, 0.f, 0.f);
    }

    if (tid < 4) lcnt[tid] = 0;
    for (int k = tid; k < (2 * FD * HD) / 4; k += 256)
        ((float4*)sW)[k] = ((const float4*)W)[k];
    sx[nl][h] = x[node * FD + h];
    __syncthreads();

    // compaction scan (overlapped with pq compute before the next sync)
    unsigned myj[4][3]; int mc[4]; unsigned mpos[4];
    if (A) {
#pragma unroll
        for (int r = 0; r < 4; r++) {
            mc[r] = 0;
            const float* Ar = A + (size_t)(b * 4 + r) * NN;
#pragma unroll
            for (int t = 0; t < 3; t++) {
                int j = tid + t * 256;
                if (Ar[j] != 0.0f) myj[r][mc[r]++] = (unsigned)j;
            }
            mpos[r] = mc[r] ? atomicAdd(&lcnt[r], (unsigned)mc[r]) : 0u;
        }
    }

    // pq compute from smem
    float p = ba[h], q = 0.f;
#pragma unroll
    for (int f = 0; f < FD; f++) {
        float xv = sx[nl][f];
        float wi = sW[f * HD + h];
        float wd = sW[(FD + f) * HD + h];
        p = fmaf(xv, wi - wd, p);
        q = fmaf(xv, wd, q);
    }
    P[node * HD + h] = p;
    Q[node * HD + h] = q;

    if (A) {
        __syncthreads();
        if (tid == 0) {
#pragma unroll
            for (int r = 0; r < 4; r++)
                lbase[r] = atomicAdd(&g_cnt, lcnt[r]);
        }
        __syncthreads();
#pragma unroll
        for (int r = 0; r < 4; r++) {
            unsigned base = lbase[r] + mpos[r];
            unsigned rowbits = (unsigned)(b * 4 + r) << 10;
            for (int t = 0; t < mc[r]; t++)
                g_edges[base + t] = rowbits | myj[r][t];
        }
    }
}

// Lane-per-edge, scalar fp32, all per-lane state in registers; smem = weights only.
// (Proven R3 body — packed-f32x2 variants spill due to 64-bit reg-pair pressure.)
__global__ __launch_bounds__(256) void edge_kernel(
    const float* __restrict__ e,  const float* __restrict__ P,
    const float* __restrict__ Q,  const float* __restrict__ W,
    const float* __restrict__ Wb, const float* __restrict__ bb,
    float* __restrict__ out)
{
    __shared__ __align__(16) float sWe[DE * HD];   // 8 KB
    __shared__ __align__(16) float sWb[HD * HD];   // 16 KB
    __shared__ __align__(16) float sbb[HD];

    const int tid  = threadIdx.x;
    const int lane = tid & 31;
    const int warp = tid >> 5;

    for (int k = tid; k < DE * HD; k += 256) sWe[k] = W[(2 * FD) * HD + k];
    for (int k = tid; k < HD * HD; k += 256) sWb[k] = Wb[k];
    if (tid < HD) sbb[tid] = bb[tid];
    __syncthreads();

    const unsigned cnt  = g_cnt;
    const unsigned nbat = (cnt + 31u) >> 5;
    const unsigned slot   = (unsigned)warp * EGRID + blockIdx.x;
    const unsigned stride = EGRID * 8u;

    for (unsigned bat = slot; bat < nbat; bat += stride) {
        const unsigned eid = bat * 32u + (unsigned)lane;
        const bool valid = (eid < cnt);
        const unsigned pk = g_edges[valid ? eid : (cnt - 1u)];
        const int i = (int)(pk >> 10);
        const int j = (int)(pk & 1023u);

        // e-row into registers
        float ev[DE];
        {
            const float4* ep = (const float4*)(e + ((size_t)(i * NN + j)) * DE);
#pragma unroll
            for (int q4 = 0; q4 < 8; q4++) {
                float4 v = ep[q4];
                ev[q4 * 4 + 0] = v.x; ev[q4 * 4 + 1] = v.y;
                ev[q4 * 4 + 2] = v.z; ev[q4 * 4 + 3] = v.w;
            }
        }

        // z = relu(P_i + Q_j + e @ We)
        float z[HD];
        {
            const float4* Pp = (const float4*)(P + i * HD);
            const float4* Qp = (const float4*)(Q + j * HD);
#pragma unroll
            for (int h4 = 0; h4 < 16; h4++) {
                float4 p = Pp[h4], q = Qp[h4];
                z[h4 * 4 + 0] = p.x + q.x;
                z[h4 * 4 + 1] = p.y + q.y;
                z[h4 * 4 + 2] = p.z + q.z;
                z[h4 * 4 + 3] = p.w + q.w;
            }
        }
#pragma unroll
        for (int de = 0; de < DE; de++) {
            const float evv = ev[de];
            const float4* wr = (const float4*)(sWe + de * HD);
#pragma unroll
            for (int h4 = 0; h4 < 16; h4++) {
                float4 w = wr[h4];
                z[h4 * 4 + 0] = fmaf(evv, w.x, z[h4 * 4 + 0]);
                z[h4 * 4 + 1] = fmaf(evv, w.y, z[h4 * 4 + 1]);
                z[h4 * 4 + 2] = fmaf(evv, w.z, z[h4 * 4 + 2]);
                z[h4 * 4 + 3] = fmaf(evv, w.w, z[h4 * 4 + 3]);
            }
        }
#pragma unroll
        for (int h = 0; h < HD; h++) z[h] = fmaxf(z[h], 0.f);

        // m = relu(z @ Wb + bb), computed in two 32-wide halves (reg pressure)
        float4* op = (float4*)(out + i * HD);
#pragma unroll
        for (int half = 0; half < 2; half++) {
            float m[32];
            {
                const float4* bp = (const float4*)(sbb + half * 32);
#pragma unroll
                for (int c = 0; c < 8; c++) {
                    float4 b4 = bp[c];
                    m[c * 4 + 0] = b4.x; m[c * 4 + 1] = b4.y;
                    m[c * 4 + 2] = b4.z; m[c * 4 + 3] = b4.w;
                }
            }
#pragma unroll
            for (int k = 0; k < HD; k++) {
                const float zk = z[k];
                const float4* wr = (const float4*)(sWb + k * HD + half * 32);
#pragma unroll
                for (int c = 0; c < 8; c++) {
                    float4 w = wr[c];
                    m[c * 4 + 0] = fmaf(zk, w.x, m[c * 4 + 0]);
                    m[c * 4 + 1] = fmaf(zk, w.y, m[c * 4 + 1]);
                    m[c * 4 + 2] = fmaf(zk, w.z, m[c * 4 + 2]);
                    m[c * 4 + 3] = fmaf(zk, w.w, m[c * 4 + 3]);
                }
            }
            if (valid) {
#pragma unroll
                for (int c = 0; c < 8; c++) {
                    float4 v = make_float4(fmaxf(m[c * 4 + 0], 0.f),
                                           fmaxf(m[c * 4 + 1], 0.f),
                                           fmaxf(m[c * 4 + 2], 0.f),
                                           fmaxf(m[c * 4 + 3], 0.f));
                    atomicAdd(op + half * 8 + c, v);
                }
            }
        }
    }
}

// out[i] = sigmoid( relu(x2_i @ W3 + b3) @ W4 + b4 ); also resets g_cnt for
// the next graph replay (runs last; globals are zero-init for the first run).
__global__ __launch_bounds__(128) void final_kernel(
    const float* __restrict__ x,
    const float* __restrict__ W3, const float* __restrict__ b3,
    const float* __restrict__ W4, const float* __restrict__ b4,
    float* __restrict__ out)
{
    __shared__ float sx[HD];
    __shared__ float sred[H2];
    const int i = blockIdx.x, t = threadIdx.x;
    if (i == 0 && t == 0) g_cnt = 0;
    if (t < HD) sx[t] = x[i * HD + t];
    __syncthreads();

    float h = b3[t];
#pragma unroll
    for (int k = 0; k < HD; k++)
        h = fmaf(sx[k], W3[k * H2 + t], h);
    h = fmaxf(h, 0.f);

    sred[t] = h * W4[t];
    __syncthreads();
#pragma unroll
    for (int s = 64; s > 0; s >>= 1) {
        if (t < s) sred[t] += sred[t + s];
        __syncthreads();
    }
    if (t == 0) {
        float v = sred[0] + b4[0];
        out[i] = 1.0f / (1.0f + expf(-v));
    }
}

extern "C" void kernel_launch(void* const* d_in, const int* in_sizes, int n_in,
                              void* d_out, int out_size)
{
    const float* A   = (const float*)d_in[0];
    const float* x   = (const float*)d_in[1];
    const float* e   = (const float*)d_in[2];
    const float* W1a = (const float*)d_in[3];
    const float* b1a = (const float*)d_in[4];
    const float* W1b = (const float*)d_in[5];
    const float* b1b = (const float*)d_in[6];
    const float* W2a = (const float*)d_in[7];
    const float* b2a = (const float*)d_in[8];
    const float* W2b = (const float*)d_in[9];
    const float* b2b = (const float*)d_in[10];
    const float* W3  = (const float*)d_in[11];
    const float* b3  = (const float*)d_in[12];
    const float* W4  = (const float*)d_in[13];
    const float* b4  = (const float*)d_in[14];
    float* out = (float*)d_out;

    float *P, *Q, *X1, *X2;
    cudaGetSymbolAddress((void**)&P,  g_P);
    cudaGetSymbolAddress((void**)&Q,  g_Q);
    cudaGetSymbolAddress((void**)&X1, g_X1);
    cudaGetSymbolAddress((void**)&X2, g_X2);

    // Layer 1 (prep compacts A, computes P/Q, zeroes X1)
    prep_kernel<<<NN / 4, 256>>>(A, x, W1a, b1a, P, Q, X1);
    edge_kernel<<<EGRID, 256>>>(e, P, Q, W1a, W1b, b1b, X1);
    // Layer 2 (no recompaction)
    prep_kernel<<<NN / 4, 256>>>(nullptr, X1, W2a, b2a, P, Q, X2);
    edge_kernel<<<EGRID, 256>>>(e, P, Q, W2a, W2b, b2b, X2);
    // Head (also resets g_cnt)
    final_kernel<<<NN, H2>>>(X2, W3, b3, W4, b4, out);
}